// round 16
// baseline (speedup 1.0000x reference)
#include <cuda_runtime.h>
#include <cuda_fp16.h>
#include <math_constants.h>
#include <cstdint>

// ===========================================================================
// EncodecEuclideanCodebook: x[64,2048,128] f32, embed[1024,128] f32
// out = concat( quantize[N*128] f32 , embed_ind[N] as f32 )
//
// fp16 mma.sync distance GEMM (64-bin batches, 68KB smem) + tournament top-2
// epilogue. Near-tie rows (gap < THRESH) are STREAMED to a persistent
// exact-fp32 repair kernel (148 CTAs, one per SM, high-priority stream) that
// runs CONCURRENTLY with the GEMM; gather overlaps the repair tail; fix
// patches flagged rows and restores the zero invariant for graph replays.
// ===========================================================================

#define DIMS   128
#define MAXN   (64 * 2048)
#define NBINS  1024
#define THRESH 0.10f

__device__ __half g_eh[NBINS * DIMS];
__device__ float  g_esq[NBINS];
__device__ int    g_idx[MAXN];
__device__ int    g_flagcnt;
__device__ int    g_vqdone;
__device__ int    g_taskctr;
__device__ int    g_flagged[MAXN];   // 0 = empty; row+1 once published
__device__ unsigned long long g_pack[MAXN];  // zero invariant across replays

// ---------------- helpers ---------------------------------------------------
__device__ __forceinline__ uint32_t smem_u32(const void* p) {
    uint32_t a;
    asm("{ .reg .u64 t; cvta.to.shared.u64 t, %1; cvt.u32.u64 %0, t; }" : "=r"(a) : "l"(p));
    return a;
}
__device__ __forceinline__ void cp16(uint32_t dst, const void* src) {
    asm volatile("cp.async.cg.shared.global [%0], [%1], 16;" :: "r"(dst), "l"(src));
}
__device__ __forceinline__ void cp_commit()   { asm volatile("cp.async.commit_group;" ::: "memory"); }
__device__ __forceinline__ void cp_wait_all() { asm volatile("cp.async.wait_group 0;" ::: "memory"); }
__device__ __forceinline__ void cp_wait_1()   { asm volatile("cp.async.wait_group 1;" ::: "memory"); }

__device__ __forceinline__ void ldsm4(uint32_t& r0, uint32_t& r1, uint32_t& r2, uint32_t& r3,
                                      uint32_t a) {
    asm volatile("ldmatrix.sync.aligned.m8n8.x4.shared.b16 {%0,%1,%2,%3}, [%4];"
        : "=r"(r0), "=r"(r1), "=r"(r2), "=r"(r3) : "r"(a));
}
__device__ __forceinline__ void mma16816(float* c, const uint32_t* a, uint32_t b0, uint32_t b1) {
    asm volatile("mma.sync.aligned.m16n8k16.row.col.f32.f16.f16.f32 "
        "{%0,%1,%2,%3}, {%4,%5,%6,%7}, {%8,%9}, {%0,%1,%2,%3};"
        : "+f"(c[0]), "+f"(c[1]), "+f"(c[2]), "+f"(c[3])
        : "r"(a[0]), "r"(a[1]), "r"(a[2]), "r"(a[3]), "r"(b0), "r"(b1));
}

__device__ __forceinline__ unsigned long long pack_key(float s, int bin) {
    uint32_t u = __float_as_uint(s);
    u = (u & 0x80000000u) ? ~u : (u | 0x80000000u);
    return ((unsigned long long)u << 32) | (unsigned long long)(0xFFFFFFFFu - (uint32_t)bin);
}

// merge two (max,second) pairs
__device__ __forceinline__ void merge2(float& h1, float& l1, float h2, float l2) {
    float mn = fminf(h1, h2);
    float mx = fmaxf(h1, h2);
    l1 = fmaxf(mn, fmaxf(l1, l2));
    h1 = mx;
}

// ---------------- preprocess -------------------------------------------------
__global__ void prep_embed_kernel(const float* __restrict__ embed) {
    int b = blockIdx.x * blockDim.x + threadIdx.x;
    if (b == 0) { g_flagcnt = 0; g_vqdone = 0; g_taskctr = 0; }
    if (b < NBINS) {
        float s = 0.0f;
#pragma unroll
        for (int c = 0; c < DIMS; c += 4) {
            float4 v = *reinterpret_cast<const float4*>(&embed[(size_t)b * DIMS + c]);
            s = fmaf(v.x, v.x, s); s = fmaf(v.y, v.y, s);
            s = fmaf(v.z, v.z, s); s = fmaf(v.w, v.w, s);
            __half2 h0 = __floats2half2_rn(v.x, v.y);
            __half2 h1 = __floats2half2_rn(v.z, v.w);
            uint2 u;
            u.x = *reinterpret_cast<uint32_t*>(&h0);
            u.y = *reinterpret_cast<uint32_t*>(&h1);
            reinterpret_cast<uint2*>(g_eh)[((size_t)b * DIMS + c) >> 2] = u;
        }
        g_esq[b] = s;
    }
}

// ---------------- main: fp16 MMA distance GEMM + tournament argmax ----------
#define SA        0
#define SB        32768
#define SESQ      65536
#define SMEM_MAIN 69632

__global__ void __launch_bounds__(256, 3) vq_mma_kernel(const float* __restrict__ x) {
    extern __shared__ char smem[];
    const uint32_t sb = smem_u32(smem);
    const int tid = threadIdx.x;
    const int wid = tid >> 5;
    const int lane = tid & 31;
    const int rowBase = blockIdx.x * 128;

    {
        const uint8_t* bsrc = (const uint8_t*)g_eh;
#pragma unroll
        for (int i = 0; i < 4; i++) {
            int g = tid + i * 256;
            int r = g >> 4, c = g & 15;
            cp16(sb + SB + r * 256 + ((c ^ (r & 7)) << 4), bsrc + g * 16);
        }
        cp16(sb + SESQ + tid * 16, (const uint8_t*)g_esq + tid * 16);
        cp_commit();

#pragma unroll
        for (int i = 0; i < 8; i++) {
            int g = tid + i * 256;
            int r = g >> 4, c = g & 15;
            const float4* src = reinterpret_cast<const float4*>(
                x + (size_t)(rowBase + r) * DIMS + c * 8);
            float4 v0 = src[0], v1 = src[1];
            __half2 h0 = __floats2half2_rn(v0.x, v0.y);
            __half2 h1 = __floats2half2_rn(v0.z, v0.w);
            __half2 h2 = __floats2half2_rn(v1.x, v1.y);
            __half2 h3 = __floats2half2_rn(v1.z, v1.w);
            uint4 u;
            u.x = *reinterpret_cast<uint32_t*>(&h0);
            u.y = *reinterpret_cast<uint32_t*>(&h1);
            u.z = *reinterpret_cast<uint32_t*>(&h2);
            u.w = *reinterpret_cast<uint32_t*>(&h3);
            *reinterpret_cast<uint4*>(smem + SA + r * 256 + ((c ^ (r & 7)) << 4)) = u;
        }
        cp_wait_all();
    }
    __syncthreads();

    const float* esq_s = (const float*)(smem + SESQ);
    const int m0 = wid * 16;

    float gb[2] = {-CUDART_INF_F, -CUDART_INF_F};
    float gs[2] = {-CUDART_INF_F, -CUDART_INF_F};
    int   gbat[2] = {0, 0};
    int   gcol[2] = {2 * (lane & 3), 2 * (lane & 3)};

    for (int b = 0; b < 16; b++) {
        if (b < 15) {
            const uint8_t* bsrc = (const uint8_t*)g_eh + (size_t)(b + 1) * 16384;
            uint32_t dstb = sb + SB + (uint32_t)(((b + 1) & 1)) * 16384;
#pragma unroll
            for (int i = 0; i < 4; i++) {
                int g = tid + i * 256;
                int r = g >> 4, c = g & 15;
                cp16(dstb + r * 256 + ((c ^ (r & 7)) << 4), bsrc + g * 16);
            }
            cp_commit();
        }
        const uint32_t buf = sb + SB + (uint32_t)(b & 1) * 16384;

        float acc[8][4];
#pragma unroll
        for (int i = 0; i < 8; i++) {
            acc[i][0] = 0.f; acc[i][1] = 0.f; acc[i][2] = 0.f; acc[i][3] = 0.f;
        }

#pragma unroll
        for (int ks = 0; ks < 8; ks++) {
            uint32_t a[4];
            {
                int ar = m0 + (lane & 15);
                int ac = ks * 2 + (lane >> 4);
                ldsm4(a[0], a[1], a[2], a[3], sb + SA + ar * 256 + ((ac ^ (ar & 7)) << 4));
            }
            const int mat = lane >> 3;
            const int nrb = ((mat >> 1) << 3) + (lane & 7);
            const int nc = ks * 2 + (mat & 1);
#pragma unroll
            for (int i = 0; i < 4; i++) {
                uint32_t b0, b1, b2, b3;
                int nr = i * 16 + nrb;
                ldsm4(b0, b1, b2, b3, buf + nr * 256 + ((nc ^ (nr & 7)) << 4));
                mma16816(acc[2 * i],     a, b0, b1);
                mma16816(acc[2 * i + 1], a, b2, b3);
            }
        }

        // --- epilogue: 4-bit local id packed into mantissa; FMNMX tree ---
        const int base = 2 * (lane & 3);
#pragma unroll
        for (int slot = 0; slot < 2; slot++) {
            float v[16];
#pragma unroll
            for (int nt = 0; nt < 8; nt++) {
                int c0 = b * 64 + base + nt * 8;
                float s0 = fmaf(2.f, acc[nt][2 * slot],     -esq_s[c0]);
                float s1 = fmaf(2.f, acc[nt][2 * slot + 1], -esq_s[c0 + 1]);
                v[2 * nt]     = __uint_as_float((__float_as_uint(s0) & ~15u) | (uint32_t)(15 - 2 * nt));
                v[2 * nt + 1] = __uint_as_float((__float_as_uint(s1) & ~15u) | (uint32_t)(15 - (2 * nt + 1)));
            }
            float h[8], l[8];
#pragma unroll
            for (int i = 0; i < 8; i++) {
                h[i] = fmaxf(v[2 * i], v[2 * i + 1]);
                l[i] = fminf(v[2 * i], v[2 * i + 1]);
            }
#pragma unroll
            for (int w = 4; w >= 1; w >>= 1)
#pragma unroll
                for (int i = 0; i < w; i++) merge2(h[i], l[i], h[i + w], l[i + w]);
            const float M = h[0], S = l[0];
            if (M > gb[slot]) {
                gs[slot] = fmaxf(gb[slot], S);
                gb[slot] = M;
                gbat[slot] = b;
            } else {
                gs[slot] = fmaxf(gs[slot], M);
            }
        }

        cp_wait_all();
        __syncthreads();
    }

    // quad merge (lanes 4k..4k+3 share rows); carry (batch, col) metadata
#pragma unroll
    for (int slot = 0; slot < 2; slot++) {
#pragma unroll
        for (int off = 1; off < 4; off <<= 1) {
            float ob = __shfl_down_sync(0xffffffffu, gb[slot], off, 4);
            float os = __shfl_down_sync(0xffffffffu, gs[slot], off, 4);
            int obat  = __shfl_down_sync(0xffffffffu, gbat[slot], off, 4);
            int ocol  = __shfl_down_sync(0xffffffffu, gcol[slot], off, 4);
            if (ob > gb[slot]) {
                gs[slot] = fmaxf(gb[slot], os);
                gb[slot] = ob; gbat[slot] = obat; gcol[slot] = ocol;
            } else {
                gs[slot] = fmaxf(gs[slot], ob);
            }
        }
    }
    if ((lane & 3) == 0) {
#pragma unroll
        for (int slot = 0; slot < 2; slot++) {
            int row = rowBase + m0 + (lane >> 2) + slot * 8;
            int li = 15 - (int)(__float_as_uint(gb[slot]) & 15u);
            int bin = gbat[slot] * 64 + gcol[slot] + ((li >> 1) << 3) + (li & 1);
            g_idx[row] = bin;
            if (gb[slot] - gs[slot] < THRESH) {
                int f = atomicAdd(&g_flagcnt, 1);     // reserve (returns -> complete)
                atomicExch(&g_flagged[f], row + 1);   // publish (consumer spins on this)
            }
        }
    }
    // CTA completion signal for the streaming consumer
    __syncthreads();
    if (tid == 0) {
        __threadfence();
        atomicAdd(&g_vqdone, 1);
    }
}

// ---------------- streaming repair: persistent exact fp32 --------------------
// 148 CTAs (1/SM), co-resident with vq. Tasks = (flag-group of 32) x strip.
#define RP_PITCH  132                   // floats per smem row (33 float4)
#define RP_XS     0                     // 32 rows  -> 16896 B
#define RP_ES(s)  (16896 + (s) * 33792) // 64 rows  -> 33792 B each
#define RP_SMEM   84480

__global__ void __launch_bounds__(256, 1) repair_stream_kernel(
        const float* __restrict__ x, const float* __restrict__ embed, int ntiles) {
    extern __shared__ char smem[];
    float* xs = (float*)(smem + RP_XS);
    __shared__ int sh_task, sh_cnt, sh_rows[32];
    const int tid = threadIdx.x;

    for (;;) {
        if (tid == 0) sh_task = atomicAdd(&g_taskctr, 1);
        __syncthreads();
        const int task = sh_task;
        const int g = task >> 3;
        const int strip = task & 7;
        const int binb0 = strip * 128;

        // wait until group g is fully defined (cnt passes it, or vq done)
        if (tid == 0) {
            const int need = (g + 1) * 32;
            for (;;) {
                int cnt = *(volatile int*)&g_flagcnt;
                if (cnt >= need) { sh_cnt = need; break; }
                int done = *(volatile int*)&g_vqdone;
                if (done == ntiles) { sh_cnt = *(volatile int*)&g_flagcnt; break; }
                __nanosleep(200);
            }
        }
        __syncthreads();
        int rem = sh_cnt - g * 32;
        if (rem <= 0) break;               // tasks exhausted
        if (rem > 32) rem = 32;

        // spin-collect the published row ids for this group
        if (tid < rem) {
            int v;
            do { v = *(volatile int*)&g_flagged[g * 32 + tid]; } while (v == 0);
            sh_rows[tid] = v - 1;
        }
        __syncthreads();

        // stage x rows (indirect) + es chunk 0 / chunk 1
        {
            uint32_t xsb = smem_u32(xs);
#pragma unroll
            for (int t = 0; t < 4; t++) {
                int i = tid + t * 256;
                int r = i >> 5, c = i & 31;
                int fr = (r < rem) ? r : 0;
                cp16(xsb + (r * RP_PITCH + c * 4) * 4, &x[(size_t)sh_rows[fr] * DIMS + c * 4]);
            }
            uint32_t esb = smem_u32(smem + RP_ES(0));
#pragma unroll
            for (int t = 0; t < 8; t++) {
                int i = tid + t * 256;
                int r = i >> 5, c = i & 31;
                cp16(esb + (r * RP_PITCH + c * 4) * 4, &embed[(size_t)(binb0 + r) * DIMS + c * 4]);
            }
            cp_commit();
        }
        {
            uint32_t esb = smem_u32(smem + RP_ES(1));
#pragma unroll
            for (int t = 0; t < 8; t++) {
                int i = tid + t * 256;
                int r = i >> 5, c = i & 31;
                cp16(esb + (r * RP_PITCH + c * 4) * 4, &embed[(size_t)(binb0 + 64 + r) * DIMS + c * 4]);
            }
            cp_commit();
        }

        const int rp = tid >> 4;
        const int bg = tid & 15;
        float bv0 = -CUDART_INF_F, bv1 = -CUDART_INF_F;
        int   bb0 = 0, bb1 = 0;

#pragma unroll
        for (int c = 0; c < 2; c++) {
            if (c == 0) cp_wait_1(); else cp_wait_all();
            __syncthreads();

            const float4* xs4 = (const float4*)xs;
            const float4* es4 = (const float4*)(smem + RP_ES(c));
            float a0[4] = {0.f, 0.f, 0.f, 0.f};
            float a1[4] = {0.f, 0.f, 0.f, 0.f};
#pragma unroll
            for (int k = 0; k < 32; k++) {
                float4 xa0 = xs4[(2 * rp)     * 33 + k];
                float4 xa1 = xs4[(2 * rp + 1) * 33 + k];
#pragma unroll
                for (int j = 0; j < 4; j++) {
                    float4 eb = es4[(bg + j * 16) * 33 + k];
                    a0[j] = fmaf(xa0.x, eb.x, a0[j]); a0[j] = fmaf(xa0.y, eb.y, a0[j]);
                    a0[j] = fmaf(xa0.z, eb.z, a0[j]); a0[j] = fmaf(xa0.w, eb.w, a0[j]);
                    a1[j] = fmaf(xa1.x, eb.x, a1[j]); a1[j] = fmaf(xa1.y, eb.y, a1[j]);
                    a1[j] = fmaf(xa1.z, eb.z, a1[j]); a1[j] = fmaf(xa1.w, eb.w, a1[j]);
                }
            }
#pragma unroll
            for (int j = 0; j < 4; j++) {
                int bin = binb0 + c * 64 + bg + j * 16;
                float e = __ldg(&g_esq[bin]);
                float s;
                s = fmaf(2.f, a0[j], -e);
                if (s > bv0 || (s == bv0 && bin < bb0)) { bv0 = s; bb0 = bin; }
                s = fmaf(2.f, a1[j], -e);
                if (s > bv1 || (s == bv1 && bin < bb1)) { bv1 = s; bb1 = bin; }
            }
            __syncthreads();
        }

        if (2 * rp < rem)
            atomicMax(&g_pack[g * 32 + 2 * rp], pack_key(bv0, bb0));
        if (2 * rp + 1 < rem)
            atomicMax(&g_pack[g * 32 + 2 * rp + 1], pack_key(bv1, bb1));
        __syncthreads();
    }
}

// ---------------- speculative gather (pre-repair indices) --------------------
__global__ void gather_kernel(const float* __restrict__ embed,
                              float* __restrict__ outq,
                              float* __restrict__ outi, int N) {
    int t = blockIdx.x * blockDim.x + threadIdx.x;
    int total = N * (DIMS / 4);
    if (t < total) {
        int row = t >> 5;
        int d = t & 31;
        int b = g_idx[row];
        reinterpret_cast<float4*>(outq)[(size_t)row * 32 + d] =
            reinterpret_cast<const float4*>(embed)[(size_t)b * 32 + d];
    }
    if (outi != nullptr && t < N) outi[t] = (float)g_idx[t];
}

// ---------------- fix: patch flagged rows; restore zero invariant ------------
__global__ void fix_kernel(const float* __restrict__ embed,
                           float* __restrict__ outq,
                           float* __restrict__ outi) {
    int cnt = g_flagcnt; if (cnt > MAXN) cnt = MAXN;
    const int lane = threadIdx.x & 31;
    const int warpsTotal = (gridDim.x * blockDim.x) >> 5;
    for (int f = (blockIdx.x * blockDim.x + threadIdx.x) >> 5; f < cnt; f += warpsTotal) {
        unsigned long long p = g_pack[f];
        int idx = (int)(0xFFFFFFFFu - (uint32_t)(p & 0xFFFFFFFFull));
        int row = g_flagged[f] - 1;
        g_idx[row] = idx;
        if (outq != nullptr)
            reinterpret_cast<float4*>(outq)[(size_t)row * 32 + lane] =
                reinterpret_cast<const float4*>(embed)[(size_t)idx * 32 + lane];
        if (outi != nullptr && lane == 0) outi[row] = (float)idx;
        if (lane == 0) { g_flagged[f] = 0; g_pack[f] = 0ull; }   // zero invariant
    }
}

__global__ void idx_only_kernel(int* __restrict__ out, int N) {
    int t = blockIdx.x * blockDim.x + threadIdx.x;
    if (t < N) out[t] = g_idx[t];
}

// ---------------- launch -----------------------------------------------------
extern "C" void kernel_launch(void* const* d_in, const int* in_sizes, int n_in,
                              void* d_out, int out_size) {
    const float* x = (const float*)d_in[0];
    const float* embed = (const float*)d_in[1];
    const int N = in_sizes[0] / DIMS;        // 131072
    const int ntiles = N / 128;              // 1024
    (void)n_in;

    static bool inited = false;
    static cudaStream_t s1 = nullptr;
    static cudaEvent_t evP = nullptr, evR = nullptr;
    if (!inited) {
        int loPrio, hiPrio;
        cudaDeviceGetStreamPriorityRange(&loPrio, &hiPrio);
        cudaStreamCreateWithPriority(&s1, cudaStreamNonBlocking, hiPrio);
        cudaEventCreateWithFlags(&evP, cudaEventDisableTiming);
        cudaEventCreateWithFlags(&evR, cudaEventDisableTiming);
        cudaFuncSetAttribute(vq_mma_kernel, cudaFuncAttributeMaxDynamicSharedMemorySize, SMEM_MAIN);
        cudaFuncSetAttribute(repair_stream_kernel, cudaFuncAttributeMaxDynamicSharedMemorySize, RP_SMEM);
        inited = true;
    }

    prep_embed_kernel<<<(NBINS + 255) / 256, 256>>>(embed);
    cudaEventRecord(evP, 0);
    cudaStreamWaitEvent(s1, evP, 0);
    // persistent streaming repair: resident BEFORE vq so it co-schedules (1 CTA/SM)
    repair_stream_kernel<<<148, 256, RP_SMEM, s1>>>(x, embed, ntiles);
    vq_mma_kernel<<<ntiles, 256, SMEM_MAIN>>>(x);

    const long long qElems = (long long)N * DIMS;
    if (out_size == N) {
        cudaEventRecord(evR, s1);
        cudaStreamWaitEvent(0, evR, 0);
        fix_kernel<<<256, 256>>>(embed, nullptr, nullptr);
        idx_only_kernel<<<(N + 255) / 256, 256>>>((int*)d_out, N);
        return;
    }

    float* outq = (float*)d_out;
    float* outi = (out_size >= qElems + N) ? ((float*)d_out + qElems) : nullptr;

    // gather overlaps the repair tail (needs only pre-repair g_idx)
    {
        int threadsTotal = N * (DIMS / 4);
        gather_kernel<<<(threadsTotal + 255) / 256, 256>>>(embed, outq, outi, N);
    }
    cudaEventRecord(evR, s1);
    cudaStreamWaitEvent(0, evR, 0);
    fix_kernel<<<256, 256>>>(embed, outq, outi);
}

// round 17
// speedup vs baseline: 23.4424x; 23.4424x over previous
#include <cuda_runtime.h>
#include <cuda_fp16.h>
#include <math_constants.h>
#include <cstdint>

// ===========================================================================
// EncodecEuclideanCodebook: x[64,2048,128] f32, embed[1024,128] f32
// out = concat( quantize[N*128] f32 , embed_ind[N] as f32 )
//
// fp16 mma.sync distance GEMM with 64-bin B batches (68KB smem -> 3 CTAs/SM)
// + tournament top-2 epilogue (4-bit candidate id packed in score mantissa).
// Near-tie rows (gap < THRESH = 0.09, ~7 sigma of the fp16 score-gap error)
// get exact fp32 re-argmax; speculative gather overlaps the repair on a
// forked stream; fix kernel patches flagged rows.
// ===========================================================================

#define DIMS   128
#define MAXN   (64 * 2048)
#define NBINS  1024
#define THRESH 0.09f

__device__ __half g_eh[NBINS * DIMS];
__device__ float  g_esq[NBINS];
__device__ int    g_idx[MAXN];
__device__ int    g_flagcnt;
__device__ int    g_flagged[MAXN];
__device__ unsigned long long g_pack[MAXN];

// ---------------- helpers ---------------------------------------------------
__device__ __forceinline__ uint32_t smem_u32(const void* p) {
    uint32_t a;
    asm("{ .reg .u64 t; cvta.to.shared.u64 t, %1; cvt.u32.u64 %0, t; }" : "=r"(a) : "l"(p));
    return a;
}
__device__ __forceinline__ void cp16(uint32_t dst, const void* src) {
    asm volatile("cp.async.cg.shared.global [%0], [%1], 16;" :: "r"(dst), "l"(src));
}
__device__ __forceinline__ void cp_commit()   { asm volatile("cp.async.commit_group;" ::: "memory"); }
__device__ __forceinline__ void cp_wait_all() { asm volatile("cp.async.wait_group 0;" ::: "memory"); }
__device__ __forceinline__ void cp_wait_1()   { asm volatile("cp.async.wait_group 1;" ::: "memory"); }

__device__ __forceinline__ void ldsm4(uint32_t& r0, uint32_t& r1, uint32_t& r2, uint32_t& r3,
                                      uint32_t a) {
    asm volatile("ldmatrix.sync.aligned.m8n8.x4.shared.b16 {%0,%1,%2,%3}, [%4];"
        : "=r"(r0), "=r"(r1), "=r"(r2), "=r"(r3) : "r"(a));
}
__device__ __forceinline__ void mma16816(float* c, const uint32_t* a, uint32_t b0, uint32_t b1) {
    asm volatile("mma.sync.aligned.m16n8k16.row.col.f32.f16.f16.f32 "
        "{%0,%1,%2,%3}, {%4,%5,%6,%7}, {%8,%9}, {%0,%1,%2,%3};"
        : "+f"(c[0]), "+f"(c[1]), "+f"(c[2]), "+f"(c[3])
        : "r"(a[0]), "r"(a[1]), "r"(a[2]), "r"(a[3]), "r"(b0), "r"(b1));
}

__device__ __forceinline__ unsigned long long pack_key(float s, int bin) {
    uint32_t u = __float_as_uint(s);
    u = (u & 0x80000000u) ? ~u : (u | 0x80000000u);
    return ((unsigned long long)u << 32) | (unsigned long long)(0xFFFFFFFFu - (uint32_t)bin);
}

// merge two (max,second) pairs
__device__ __forceinline__ void merge2(float& h1, float& l1, float h2, float l2) {
    float mn = fminf(h1, h2);
    float mx = fmaxf(h1, h2);
    l1 = fmaxf(mn, fmaxf(l1, l2));
    h1 = mx;
}

// ---------------- preprocess -------------------------------------------------
__global__ void prep_embed_kernel(const float* __restrict__ embed) {
    int b = blockIdx.x * blockDim.x + threadIdx.x;
    if (b == 0) g_flagcnt = 0;
    if (b < NBINS) {
        float s = 0.0f;
#pragma unroll
        for (int c = 0; c < DIMS; c += 4) {
            float4 v = *reinterpret_cast<const float4*>(&embed[(size_t)b * DIMS + c]);
            s = fmaf(v.x, v.x, s); s = fmaf(v.y, v.y, s);
            s = fmaf(v.z, v.z, s); s = fmaf(v.w, v.w, s);
            __half2 h0 = __floats2half2_rn(v.x, v.y);
            __half2 h1 = __floats2half2_rn(v.z, v.w);
            uint2 u;
            u.x = *reinterpret_cast<uint32_t*>(&h0);
            u.y = *reinterpret_cast<uint32_t*>(&h1);
            reinterpret_cast<uint2*>(g_eh)[((size_t)b * DIMS + c) >> 2] = u;
        }
        g_esq[b] = s;
    }
}

// ---------------- main: fp16 MMA distance GEMM + tournament argmax ----------
// CTA: 128 rows x 1024 bins in 16 batches of 64 bins. 8 warps, each warp
// 16 rows x 64 bins/batch. smem 68KB -> 3 CTAs/SM.
#define SA        0
#define SB        32768
#define SESQ      65536
#define SMEM_MAIN 69632

__global__ void __launch_bounds__(256, 3) vq_mma_kernel(const float* __restrict__ x) {
    extern __shared__ char smem[];
    const uint32_t sb = smem_u32(smem);
    const int tid = threadIdx.x;
    const int wid = tid >> 5;
    const int lane = tid & 31;
    const int rowBase = blockIdx.x * 128;

    // stage B batch 0 (16KB) + esq via cp.async; A converted fp32->fp16
    {
        const uint8_t* bsrc = (const uint8_t*)g_eh;
#pragma unroll
        for (int i = 0; i < 4; i++) {
            int g = tid + i * 256;           // 0..1023 = 64 rows x 16 chunks
            int r = g >> 4, c = g & 15;
            cp16(sb + SB + r * 256 + ((c ^ (r & 7)) << 4), bsrc + g * 16);
        }
        cp16(sb + SESQ + tid * 16, (const uint8_t*)g_esq + tid * 16);
        cp_commit();

#pragma unroll
        for (int i = 0; i < 8; i++) {
            int g = tid + i * 256;
            int r = g >> 4, c = g & 15;
            const float4* src = reinterpret_cast<const float4*>(
                x + (size_t)(rowBase + r) * DIMS + c * 8);
            float4 v0 = src[0], v1 = src[1];
            __half2 h0 = __floats2half2_rn(v0.x, v0.y);
            __half2 h1 = __floats2half2_rn(v0.z, v0.w);
            __half2 h2 = __floats2half2_rn(v1.x, v1.y);
            __half2 h3 = __floats2half2_rn(v1.z, v1.w);
            uint4 u;
            u.x = *reinterpret_cast<uint32_t*>(&h0);
            u.y = *reinterpret_cast<uint32_t*>(&h1);
            u.z = *reinterpret_cast<uint32_t*>(&h2);
            u.w = *reinterpret_cast<uint32_t*>(&h3);
            *reinterpret_cast<uint4*>(smem + SA + r * 256 + ((c ^ (r & 7)) << 4)) = u;
        }
        cp_wait_all();
    }
    __syncthreads();

    const float* esq_s = (const float*)(smem + SESQ);
    const int m0 = wid * 16;

    float gb[2] = {-CUDART_INF_F, -CUDART_INF_F};
    float gs[2] = {-CUDART_INF_F, -CUDART_INF_F};
    int   gbat[2] = {0, 0};
    int   gcol[2] = {2 * (lane & 3), 2 * (lane & 3)};

    for (int b = 0; b < 16; b++) {
        if (b < 15) {
            const uint8_t* bsrc = (const uint8_t*)g_eh + (size_t)(b + 1) * 16384;
            uint32_t dstb = sb + SB + (uint32_t)(((b + 1) & 1)) * 16384;
#pragma unroll
            for (int i = 0; i < 4; i++) {
                int g = tid + i * 256;
                int r = g >> 4, c = g & 15;
                cp16(dstb + r * 256 + ((c ^ (r & 7)) << 4), bsrc + g * 16);
            }
            cp_commit();
        }
        const uint32_t buf = sb + SB + (uint32_t)(b & 1) * 16384;

        float acc[8][4];
#pragma unroll
        for (int i = 0; i < 8; i++) {
            acc[i][0] = 0.f; acc[i][1] = 0.f; acc[i][2] = 0.f; acc[i][3] = 0.f;
        }

#pragma unroll
        for (int ks = 0; ks < 8; ks++) {
            uint32_t a[4];
            {
                int ar = m0 + (lane & 15);
                int ac = ks * 2 + (lane >> 4);
                ldsm4(a[0], a[1], a[2], a[3], sb + SA + ar * 256 + ((ac ^ (ar & 7)) << 4));
            }
            const int mat = lane >> 3;
            const int nrb = ((mat >> 1) << 3) + (lane & 7);
            const int nc = ks * 2 + (mat & 1);
#pragma unroll
            for (int i = 0; i < 4; i++) {
                uint32_t b0, b1, b2, b3;
                int nr = i * 16 + nrb;
                ldsm4(b0, b1, b2, b3, buf + nr * 256 + ((nc ^ (nr & 7)) << 4));
                mma16816(acc[2 * i],     a, b0, b1);
                mma16816(acc[2 * i + 1], a, b2, b3);
            }
        }

        // --- epilogue: 4-bit local id packed into mantissa; FMNMX tree ---
        const int base = 2 * (lane & 3);
#pragma unroll
        for (int slot = 0; slot < 2; slot++) {
            float v[16];
#pragma unroll
            for (int nt = 0; nt < 8; nt++) {
                int c0 = b * 64 + base + nt * 8;
                float s0 = fmaf(2.f, acc[nt][2 * slot],     -esq_s[c0]);
                float s1 = fmaf(2.f, acc[nt][2 * slot + 1], -esq_s[c0 + 1]);
                v[2 * nt]     = __uint_as_float((__float_as_uint(s0) & ~15u) | (uint32_t)(15 - 2 * nt));
                v[2 * nt + 1] = __uint_as_float((__float_as_uint(s1) & ~15u) | (uint32_t)(15 - (2 * nt + 1)));
            }
            float h[8], l[8];
#pragma unroll
            for (int i = 0; i < 8; i++) {
                h[i] = fmaxf(v[2 * i], v[2 * i + 1]);
                l[i] = fminf(v[2 * i], v[2 * i + 1]);
            }
#pragma unroll
            for (int w = 4; w >= 1; w >>= 1)
#pragma unroll
                for (int i = 0; i < w; i++) merge2(h[i], l[i], h[i + w], l[i + w]);
            const float M = h[0], S = l[0];
            if (M > gb[slot]) {
                gs[slot] = fmaxf(gb[slot], S);
                gb[slot] = M;
                gbat[slot] = b;
            } else {
                gs[slot] = fmaxf(gs[slot], M);
            }
        }

        cp_wait_all();
        __syncthreads();
    }

    // quad merge (lanes 4k..4k+3 share rows); carry (batch, col) metadata
#pragma unroll
    for (int slot = 0; slot < 2; slot++) {
#pragma unroll
        for (int off = 1; off < 4; off <<= 1) {
            float ob = __shfl_down_sync(0xffffffffu, gb[slot], off, 4);
            float os = __shfl_down_sync(0xffffffffu, gs[slot], off, 4);
            int obat  = __shfl_down_sync(0xffffffffu, gbat[slot], off, 4);
            int ocol  = __shfl_down_sync(0xffffffffu, gcol[slot], off, 4);
            if (ob > gb[slot]) {
                gs[slot] = fmaxf(gb[slot], os);
                gb[slot] = ob; gbat[slot] = obat; gcol[slot] = ocol;
            } else {
                gs[slot] = fmaxf(gs[slot], ob);
            }
        }
    }
    if ((lane & 3) == 0) {
#pragma unroll
        for (int slot = 0; slot < 2; slot++) {
            int row = rowBase + m0 + (lane >> 2) + slot * 8;
            int li = 15 - (int)(__float_as_uint(gb[slot]) & 15u);
            int bin = gbat[slot] * 64 + gcol[slot] + ((li >> 1) << 3) + (li & 1);
            g_idx[row] = bin;
            if (gb[slot] - gs[slot] < THRESH) {
                int f = atomicAdd(&g_flagcnt, 1);
                g_flagged[f] = row; g_pack[f] = 0ull;
            }
        }
    }
}

// ---------------- repair: task-parallel exact fp32 ---------------------------
#define RP_PITCH  132                   // floats per smem row (33 float4)
#define RP_XS     0                     // 32 rows  -> 16896 B
#define RP_ES(s)  (16896 + (s) * 33792) // 64 rows  -> 33792 B each
#define RP_SMEM   84480

__global__ void __launch_bounds__(256, 2) repair2_kernel(const float* __restrict__ x,
                                                         const float* __restrict__ embed) {
    extern __shared__ char smem[];
    float* xs = (float*)(smem + RP_XS);
    const int tid = threadIdx.x;
    int cnt = g_flagcnt; if (cnt > MAXN) cnt = MAXN;
    const int ngroups = (cnt + 31) >> 5;
    const int ntasks = ngroups * 8;

    for (int task = blockIdx.x; task < ntasks; task += gridDim.x) {
        const int g = task >> 3;
        const int strip = task & 7;
        const int rem = cnt - g * 32;
        const int binb0 = strip * 128;

        {
            uint32_t xsb = smem_u32(xs);
#pragma unroll
            for (int t = 0; t < 4; t++) {
                int i = tid + t * 256;
                int r = i >> 5, c = i & 31;
                int fr = (r < rem) ? r : 0;
                int grow = g_flagged[g * 32 + fr];
                cp16(xsb + (r * RP_PITCH + c * 4) * 4, &x[(size_t)grow * DIMS + c * 4]);
            }
            uint32_t esb = smem_u32(smem + RP_ES(0));
#pragma unroll
            for (int t = 0; t < 8; t++) {
                int i = tid + t * 256;
                int r = i >> 5, c = i & 31;
                cp16(esb + (r * RP_PITCH + c * 4) * 4, &embed[(size_t)(binb0 + r) * DIMS + c * 4]);
            }
            cp_commit();
        }
        {
            uint32_t esb = smem_u32(smem + RP_ES(1));
#pragma unroll
            for (int t = 0; t < 8; t++) {
                int i = tid + t * 256;
                int r = i >> 5, c = i & 31;
                cp16(esb + (r * RP_PITCH + c * 4) * 4, &embed[(size_t)(binb0 + 64 + r) * DIMS + c * 4]);
            }
            cp_commit();
        }

        const int rp = tid >> 4;
        const int bg = tid & 15;
        float bv0 = -CUDART_INF_F, bv1 = -CUDART_INF_F;
        int   bb0 = 0, bb1 = 0;

#pragma unroll
        for (int c = 0; c < 2; c++) {
            if (c == 0) cp_wait_1(); else cp_wait_all();
            __syncthreads();

            const float4* xs4 = (const float4*)xs;
            const float4* es4 = (const float4*)(smem + RP_ES(c));
            float a0[4] = {0.f, 0.f, 0.f, 0.f};
            float a1[4] = {0.f, 0.f, 0.f, 0.f};
#pragma unroll
            for (int k = 0; k < 32; k++) {
                float4 xa0 = xs4[(2 * rp)     * 33 + k];
                float4 xa1 = xs4[(2 * rp + 1) * 33 + k];
#pragma unroll
                for (int j = 0; j < 4; j++) {
                    float4 eb = es4[(bg + j * 16) * 33 + k];
                    a0[j] = fmaf(xa0.x, eb.x, a0[j]); a0[j] = fmaf(xa0.y, eb.y, a0[j]);
                    a0[j] = fmaf(xa0.z, eb.z, a0[j]); a0[j] = fmaf(xa0.w, eb.w, a0[j]);
                    a1[j] = fmaf(xa1.x, eb.x, a1[j]); a1[j] = fmaf(xa1.y, eb.y, a1[j]);
                    a1[j] = fmaf(xa1.z, eb.z, a1[j]); a1[j] = fmaf(xa1.w, eb.w, a1[j]);
                }
            }
#pragma unroll
            for (int j = 0; j < 4; j++) {
                int bin = binb0 + c * 64 + bg + j * 16;
                float e = __ldg(&g_esq[bin]);
                float s;
                s = fmaf(2.f, a0[j], -e);
                if (s > bv0 || (s == bv0 && bin < bb0)) { bv0 = s; bb0 = bin; }
                s = fmaf(2.f, a1[j], -e);
                if (s > bv1 || (s == bv1 && bin < bb1)) { bv1 = s; bb1 = bin; }
            }
            __syncthreads();
        }

        if (2 * rp < rem)
            atomicMax(&g_pack[g * 32 + 2 * rp], pack_key(bv0, bb0));
        if (2 * rp + 1 < rem)
            atomicMax(&g_pack[g * 32 + 2 * rp + 1], pack_key(bv1, bb1));
        __syncthreads();
    }
}

// ---------------- speculative gather (pre-repair indices) --------------------
__global__ void gather_kernel(const float* __restrict__ embed,
                              float* __restrict__ outq,
                              float* __restrict__ outi, int N) {
    int t = blockIdx.x * blockDim.x + threadIdx.x;
    int total = N * (DIMS / 4);
    if (t < total) {
        int row = t >> 5;
        int d = t & 31;
        int b = g_idx[row];
        reinterpret_cast<float4*>(outq)[(size_t)row * 32 + d] =
            reinterpret_cast<const float4*>(embed)[(size_t)b * 32 + d];
    }
    if (outi != nullptr && t < N) outi[t] = (float)g_idx[t];
}

// ---------------- fix: patch flagged rows after join -------------------------
__global__ void fix_kernel(const float* __restrict__ embed,
                           float* __restrict__ outq,
                           float* __restrict__ outi) {
    int cnt = g_flagcnt; if (cnt > MAXN) cnt = MAXN;
    const int lane = threadIdx.x & 31;
    const int warpsTotal = (gridDim.x * blockDim.x) >> 5;
    for (int f = (blockIdx.x * blockDim.x + threadIdx.x) >> 5; f < cnt; f += warpsTotal) {
        unsigned long long p = g_pack[f];
        int idx = (int)(0xFFFFFFFFu - (uint32_t)(p & 0xFFFFFFFFull));
        int row = g_flagged[f];
        g_idx[row] = idx;
        if (outq != nullptr)
            reinterpret_cast<float4*>(outq)[(size_t)row * 32 + lane] =
                reinterpret_cast<const float4*>(embed)[(size_t)idx * 32 + lane];
        if (outi != nullptr && lane == 0) outi[row] = (float)idx;
    }
}

__global__ void idx_only_kernel(int* __restrict__ out, int N) {
    int t = blockIdx.x * blockDim.x + threadIdx.x;
    if (t < N) out[t] = g_idx[t];
}

// ---------------- launch -----------------------------------------------------
extern "C" void kernel_launch(void* const* d_in, const int* in_sizes, int n_in,
                              void* d_out, int out_size) {
    const float* x = (const float*)d_in[0];
    const float* embed = (const float*)d_in[1];
    const int N = in_sizes[0] / DIMS;        // 131072
    (void)n_in;

    static bool inited = false;
    static cudaStream_t s1 = nullptr;
    static cudaEvent_t evA = nullptr, evB = nullptr;
    if (!inited) {
        cudaStreamCreateWithFlags(&s1, cudaStreamNonBlocking);
        cudaEventCreateWithFlags(&evA, cudaEventDisableTiming);
        cudaEventCreateWithFlags(&evB, cudaEventDisableTiming);
        cudaFuncSetAttribute(vq_mma_kernel, cudaFuncAttributeMaxDynamicSharedMemorySize, SMEM_MAIN);
        cudaFuncSetAttribute(repair2_kernel, cudaFuncAttributeMaxDynamicSharedMemorySize, RP_SMEM);
        inited = true;
    }

    prep_embed_kernel<<<(NBINS + 255) / 256, 256>>>(embed);
    vq_mma_kernel<<<N / 128, 256, SMEM_MAIN>>>(x);

    const long long qElems = (long long)N * DIMS;
    if (out_size == N) {
        repair2_kernel<<<592, 256, RP_SMEM>>>(x, embed);
        fix_kernel<<<256, 256>>>(embed, nullptr, nullptr);
        idx_only_kernel<<<(N + 255) / 256, 256>>>((int*)d_out, N);
        return;
    }

    float* outq = (float*)d_out;
    float* outi = (out_size >= qElems + N) ? ((float*)d_out + qElems) : nullptr;

    // fork: speculative gather (side stream) || exact repair (main stream)
    cudaEventRecord(evA, 0);
    cudaStreamWaitEvent(s1, evA, 0);
    {
        int threadsTotal = N * (DIMS / 4);
        gather_kernel<<<(threadsTotal + 255) / 256, 256, 0, s1>>>(embed, outq, outi, N);
    }
    repair2_kernel<<<592, 256, RP_SMEM>>>(x, embed);
    cudaEventRecord(evB, s1);
    cudaStreamWaitEvent(0, evB, 0);
    fix_kernel<<<256, 256>>>(embed, outq, outi);
}